// round 16
// baseline (speedup 1.0000x reference)
#include <cuda_runtime.h>
#include <math.h>

#define BB 2
#define QQ 75
#define NN 5
#define KK 1
#define TT 196
#define CC 384
#define HH 1536
#define KT 196
#define BQ 150
#define TEMPF 10.0f

#define MCH 7          // t-chunks for fused mean+ns pass (28 rows)
#define SCH 5          // t-chunks for shot map_s pass (40/36 rows)
#define HCH 16         // hidden chunks for MLP (96 units)
#define HCW 96
#define TQ 7           // t-chunk for main pass
#define NCHK 28        // TT / TQ
#define QG 15          // queries per group
#define NQG 5          // QQ / QG
#define NW 12          // warps per block (384 threads)
#define NFIN (BB + BB*NN)   // 12 MLP-finish tasks

// ---- task stream (order: T0,T1,T5a,T2,T3,T5b,T4,T6) ----
#define T0N (BB*NN*MCH)            // 70  mean+ns
#define T1N (BB*NN)                // 10  xs2_hat
#define TAN (BB*NCHK*NQG)          // 280 main num/SIM (T5a, dep-free body)
#define T2N ((BB + BB*NN)*HCH)     // 192 MLP partials
#define T3N NFIN                   // 12  MLP finish
#define TBN (BB*NCHK*NQG)          // 280 main map_q (T5b)
#define T4N (BB*NN*SCH)            // 50  shot map_s
#define T6N BQ                     // 150 finals
#define T0E T0N                    // 70
#define T1E (T0E + T1N)            // 80
#define TAE (T1E + TAN)            // 360
#define T2E (TAE + T2N)            // 552
#define T3E (T2E + T3N)            // 564
#define TBE (T3E + TBN)            // 844
#define T4E (TBE + T4N)            // 894
#define T6E (T4E + T6N)            // 1044
#define SHOT_TGT (T4N + T1N)       // 60
#define BQ_TGT (2*NCHK)            // 56 (28 T5a + 28 T5b per bq)

// ---- dynamic smem (floats): T6 dominates: 980+7680+252+21 = 8933 ----
#define DYN_FLOATS 8960
#define DYN_BYTES  (DYN_FLOATS * 4)

typedef unsigned long long u64;

// ---------------- persistent scratch ----------------
__device__ float g_mean_part[BB*NN*MCH*CC];
__device__ float g_mlp_part[(BB + BB*NN)*HCH*CC];
__device__ float g_wt[BB*CC];
__device__ float g_wc[BB*NN*CC];
__device__ float g_ns[BB*NN*KT];
__device__ float g_shot_part[BB*NN*SCH*CC];
__device__ float g_xs2_hat[BB*NN*CC];
__device__ float g_smq[BQ*NN*TT];
__device__ float g_mx_part[NCHK*BQ*NN];
__device__ unsigned g_bar_cnt;
__device__ unsigned g_bar_gen;
__device__ unsigned g_task;                 // dynamic task counter
__device__ unsigned g_meanbn_done[BB*NN];   // -> 7 each
__device__ unsigned g_meanb_done[BB];       // -> 35 each
__device__ unsigned g_mlprow_done[NFIN];    // -> 16 each
__device__ unsigned g_wcwt_done;            // -> 12
__device__ unsigned g_shot_done;            // -> 60
__device__ unsigned g_bq_done[BQ];          // -> 56 each

template<int NV>
__device__ __forceinline__ void warpRed(float* v) {
#pragma unroll
    for (int off = 16; off; off >>= 1) {
#pragma unroll
        for (int k = 0; k < NV; k++)
            v[k] += __shfl_xor_sync(0xffffffffu, v[k], off);
    }
}

template<int NV>
__device__ __forceinline__ void segRed8(float* v) {
#pragma unroll
    for (int off = 4; off; off >>= 1) {
#pragma unroll
        for (int k = 0; k < NV; k++)
            v[k] += __shfl_xor_sync(0xffffffffu, v[k], off);
    }
}

__device__ __forceinline__ void ffma2(u64& d, u64 a, u64 b) {
    asm("fma.rn.f32x2 %0, %1, %2, %0;" : "+l"(d) : "l"(a), "l"(b));
}
__device__ __forceinline__ float upsum(u64 v) {
    float lo, hi;
    asm("mov.b64 {%0, %1}, %2;" : "=f"(lo), "=f"(hi) : "l"(v));
    return lo + hi;
}
__device__ __forceinline__ void unpk2(u64 v, float& lo, float& hi) {
    asm("mov.b64 {%0, %1}, %2;" : "=f"(lo), "=f"(hi) : "l"(v));
}
__device__ __forceinline__ u64 pk2(float a, float b) {
    u64 r;
    asm("mov.b64 %0, {%1, %2};" : "=l"(r) : "f"(a), "f"(b));
    return r;
}
__device__ __forceinline__ void pfL2(const void* p) {
    asm volatile("prefetch.global.L2 [%0];" :: "l"(p));
}

__device__ __forceinline__ float sigm(float x) {
    return 1.0f / (1.0f + __expf(-x));
}

__device__ __forceinline__ void gridBar() {
    __syncthreads();
    if (threadIdx.x == 0) {
        __threadfence();
        unsigned gen = *(volatile unsigned*)&g_bar_gen;
        if (atomicAdd(&g_bar_cnt, 1u) == gridDim.x - 1u) {
            g_bar_cnt = 0u;
            __threadfence();
            atomicAdd(&g_bar_gen, 1u);
        } else {
            while (*(volatile unsigned*)&g_bar_gen == gen) __nanosleep(64);
        }
        __threadfence();
    }
    __syncthreads();
}

__device__ __forceinline__ void waitCnt(unsigned* c, unsigned target) {
    if (threadIdx.x == 0) {
        while (*(volatile unsigned*)c < target) __nanosleep(32);
    }
    __syncthreads();
}

__device__ __forceinline__ void signal1(unsigned* c) {
    __threadfence();
    __syncthreads();
    if (threadIdx.x == 0) atomicAdd(c, 1u);
}

__global__ __launch_bounds__(384, 2) void kFused(
    const float* __restrict__ fshot, const float* __restrict__ fq,
    const float* __restrict__ x_shot, const float* __restrict__ xq_in,
    const float* __restrict__ w1t, const float* __restrict__ b1t,
    const float* __restrict__ w2t, const float* __restrict__ b2t,
    const float* __restrict__ w1c, const float* __restrict__ b1c,
    const float* __restrict__ w2c, const float* __restrict__ b2c,
    float* __restrict__ out) {
    extern __shared__ float dyn[];
    __shared__ int s_task;
    const int tid = threadIdx.x;
    const int w = tid >> 5, lane = tid & 31;
    const size_t NSTRIDE = (size_t)KT * CC;   // fshot n-stride

    while (1) {
        __syncthreads();
        if (tid == 0) s_task = (int)atomicAdd(&g_task, 1u);
        __syncthreads();
        int task = s_task;
        if (task >= T6E) break;

        if (task < T0E) {
            // ===== T0: fused mean + ns partials =====
            int bn = task / MCH, ch = task % MCH;
            int t0 = ch * 28;
            float* PW = dyn;
            float acc[12];
#pragma unroll
            for (int e = 0; e < 12; e++) acc[e] = 0.0f;
            for (int t = t0 + w; t < t0 + 28; t += NW) {
                const float* fp = fshot + ((size_t)bn * KT + t) * CC + 4 * lane;
                float fv[12];
#pragma unroll
                for (int j = 0; j < 3; j++) {
                    float4 u = *(const float4*)(fp + 128 * j);
                    fv[4*j] = u.x; fv[4*j+1] = u.y; fv[4*j+2] = u.z; fv[4*j+3] = u.w;
                }
                float r[1] = {0.0f};
#pragma unroll
                for (int e = 0; e < 12; e++) r[0] += fv[e] * fv[e];
                warpRed<1>(r);
                if (lane == 0) g_ns[bn * KT + t] = sqrtf(r[0]);
#pragma unroll
                for (int e = 0; e < 12; e++) acc[e] += fv[e];
            }
#pragma unroll
            for (int e = 0; e < 12; e++) {
                int c = 128 * (e >> 2) + (lane << 2) + (e & 3);
                PW[w * CC + c] = acc[e];
            }
            __syncthreads();
            float s = 0.0f;
#pragma unroll
            for (int ww = 0; ww < NW; ww++) s += PW[ww * CC + tid];
            g_mean_part[(bn * MCH + ch) * CC + tid] = s;
            __threadfence();
            __syncthreads();
            if (tid == 0) {
                atomicAdd(&g_meanbn_done[bn], 1u);
                atomicAdd(&g_meanb_done[bn / NN], 1u);
            }
        } else if (task < T1E) {
            // ===== T1: plain prototype =====
            int bn = task - T0E;
            float xm = x_shot[(size_t)bn * CC + tid];  // KK=1
            float r[1] = {xm * xm};
            warpRed<1>(r);
            if (lane == 0) dyn[w] = r[0];
            __syncthreads();
            float tot = 0.0f;
#pragma unroll
            for (int ww = 0; ww < NW; ww++) tot += dyn[ww];
            g_xs2_hat[bn * CC + tid] = xm / fmaxf(sqrtf(tot), 1e-12f);
            signal1(&g_shot_done);
        } else if (task < TAE) {
            // ===== T5a: num dots + SIM/mx — dep-free until the tail =====
            int m = task - T1E;
            int b = m / (NCHK * NQG);
            int rem = m % (NCHK * NQG);
            int chunk = rem / NQG, qg = rem % NQG;
            int t0c = chunk * TQ;
            int q0 = b * QQ + qg * QG;
            float* SIMN = dyn;                  // QG*NN*TQ raw numerators = 525
            float* NQV  = dyn + QG*NN*TQ;       // QG*TQ = 105
            float* NSS  = NQV + QG*TQ;          // NN*TQ = 35

            const int g8 = lane >> 3, l8 = lane & 7;
            for (int base = w * 4; base < QG * TQ; base += NW * 4) {
                int item = base + g8;
                bool valid = item < QG * TQ;
                int it = valid ? item : QG * TQ - 1;
                int trel = it / QG, qi = it % QG;
                const float* fp = fq + ((size_t)(q0 + qi) * TT + t0c + trel) * CC + l8 * 4;
                const float* sp = fshot + (((size_t)(b * NN)) * KT + t0c + trel) * CC + l8 * 4;
                u64 rp[6];
#pragma unroll
                for (int k = 0; k < 6; k++) rp[k] = 0ull;
#pragma unroll 4
                for (int i = 0; i < 12; i++) {
                    ulonglong2 a = *(const ulonglong2*)(fp + i * 32);
                    ffma2(rp[0], a.x, a.x);
                    ffma2(rp[0], a.y, a.y);
#pragma unroll
                    for (int n = 0; n < NN; n++) {
                        ulonglong2 u = *(const ulonglong2*)(sp + n * NSTRIDE + i * 32);
                        ffma2(rp[1 + n], a.x, u.x);
                        ffma2(rp[1 + n], a.y, u.y);
                    }
                }
                float r[6];
#pragma unroll
                for (int k = 0; k < 6; k++) r[k] = upsum(rp[k]);
                segRed8<6>(r);
                if (l8 == 0 && valid) {
                    NQV[qi * TQ + trel] = sqrtf(r[0]);
#pragma unroll
                    for (int n = 0; n < NN; n++)
                        SIMN[(qi * NN + n) * TQ + trel] = r[1 + n];
                }
            }
            // tail: wait for ns of this batch
            waitCnt(&g_meanb_done[b], NN*MCH);
            if (tid < NN * TQ) {
                int n = tid / TQ, t = tid % TQ;
                NSS[tid] = g_ns[(b * NN + n) * KT + t0c + t];
            }
            __syncthreads();
            if (tid < QG * NN) {
                int qi = tid / NN, n = tid % NN;
                float mm = -3.4e38f;
#pragma unroll
                for (int t = 0; t < TQ; t++) {
                    float den = fmaxf(NQV[qi * TQ + t] * NSS[n * TQ + t], 1e-8f);
                    mm = fmaxf(mm, SIMN[(qi * NN + n) * TQ + t] / den);
                }
                g_mx_part[((size_t)chunk * BQ + q0 + qi) * NN + n] = mm;
            }
            __threadfence();
            __syncthreads();
            if (tid < QG) atomicAdd(&g_bq_done[q0 + tid], 1u);
        } else if (task < T2E) {
            // ===== T2: MLP partials (prefetch, wait only needed means) =====
            int s2 = task - TAE;
            int row = s2 / HCH, ch = s2 % HCH;
            float* SX = dyn; float* HP = dyn + CC; float* HID = dyn + CC + 8*HCW;
            const float *w1, *b1, *w2;
            if (row < BB) { w1 = w1t; b1 = b1t; w2 = w2t; }
            else          { w1 = w1c; b1 = b1c; w2 = w2c; }

            int ce = tid / 48, jp = tid % 48, j0 = ch * HCW;
            const float* w1b = w1 + j0 + jp * 2;
            const float* w2p = w2 + (size_t)j0 * CC + tid;
#pragma unroll 8
            for (int c = 0; c < 48; c++) pfL2(w1b + (size_t)(ce * 48 + c) * HH);
#pragma unroll 8
            for (int j = ce; j < HCW; j += 8) pfL2(w2p + (size_t)j * CC);

            if (tid == 0) {
                if (row < BB) {
                    while (*(volatile unsigned*)&g_meanb_done[row] < (unsigned)(NN*MCH)) __nanosleep(32);
                } else {
                    while (*(volatile unsigned*)&g_meanbn_done[row - BB] < (unsigned)MCH) __nanosleep(32);
                }
            }
            __syncthreads();

            if (row < BB) {
                float s = 0.0f;
#pragma unroll
                for (int n = 0; n < NN; n++)
#pragma unroll
                    for (int c2 = 0; c2 < MCH; c2++)
                        s += g_mean_part[((row * NN + n) * MCH + c2) * CC + tid];
                SX[tid] = s * (1.0f / (KT * NN));
            } else {
                int r = row - BB;
                float s = 0.0f;
#pragma unroll
                for (int c2 = 0; c2 < MCH; c2++)
                    s += g_mean_part[(r * MCH + c2) * CC + tid];
                SX[tid] = s * (1.0f / KT);
            }
            __syncthreads();

            u64 hp2 = 0ull;
#pragma unroll 8
            for (int c = 0; c < 48; c++) {
                float x = SX[ce * 48 + c];
                u64 wv = *(const u64*)(w1b + (size_t)(ce * 48 + c) * HH);
                ffma2(hp2, pk2(x, x), wv);
            }
            {
                float h0, h1;
                unpk2(hp2, h0, h1);
                HP[ce * HCW + jp * 2]     = h0;
                HP[ce * HCW + jp * 2 + 1] = h1;
            }
            __syncthreads();
            if (tid < HCW) {
                float s = b1[j0 + tid];
#pragma unroll
                for (int e = 0; e < 8; e++) s += HP[e * HCW + tid];
                HID[tid] = fmaxf(s, 0.0f);
            }
            __syncthreads();

            float o = 0.0f;
#pragma unroll 8
            for (int j = 0; j < HCW; j++) o += HID[j] * w2p[(size_t)j * CC];
            g_mlp_part[(size_t)s2 * CC + tid] = o;
            signal1(&g_mlprow_done[row]);
        } else if (task < T3E) {
            // ===== T3: MLP finish (own row only) =====
            int row = task - T2E;
            waitCnt(&g_mlprow_done[row], HCH);
            float o = (row < BB) ? b2t[tid] : b2c[tid];
#pragma unroll
            for (int c2 = 0; c2 < HCH; c2++)
                o += g_mlp_part[(size_t)(row * HCH + c2) * CC + tid];
            if (row < BB) g_wt[row * CC + tid] = o;
            else          g_wc[(row - BB) * CC + tid] = sigm(o);
            signal1(&g_wcwt_done);
        } else if (task < TBE) {
            // ===== T5b: map_q dots + smq (waits wc/wt) =====
            int m = task - T3E;
            int b = m / (NCHK * NQG);
            int rem = m % (NCHK * NQG);
            int chunk = rem / NQG, qg = rem % NQG;
            int t0c = chunk * TQ;
            int q0 = b * QQ + qg * QG;
            float* VV = dyn;                    // NN*CC
            waitCnt(&g_wcwt_done, NFIN);
            {
                float wtb = g_wt[b * CC + tid];
#pragma unroll
                for (int n = 0; n < NN; n++)
                    VV[n * CC + tid] = g_wc[(b * NN + n) * CC + tid] * wtb;
            }
            __syncthreads();

            const int g8 = lane >> 3, l8 = lane & 7;
            for (int base = w * 4; base < QG * TQ; base += NW * 4) {
                int item = base + g8;
                bool valid = item < QG * TQ;
                int it = valid ? item : QG * TQ - 1;
                int trel = it / QG, qi = it % QG;
                const float* fp = fq + ((size_t)(q0 + qi) * TT + t0c + trel) * CC + l8 * 4;
                u64 rp[5];
#pragma unroll
                for (int k = 0; k < 5; k++) rp[k] = 0ull;
#pragma unroll 4
                for (int i = 0; i < 12; i++) {
                    ulonglong2 a = *(const ulonglong2*)(fp + i * 32);
#pragma unroll
                    for (int n = 0; n < NN; n++) {
                        ulonglong2 v = *(const ulonglong2*)(VV + n * CC + i * 32 + l8 * 4);
                        ffma2(rp[n], a.x, v.x);
                        ffma2(rp[n], a.y, v.y);
                    }
                }
                float r[5];
#pragma unroll
                for (int k = 0; k < 5; k++) r[k] = upsum(rp[k]);
                segRed8<5>(r);
                if (l8 == 0 && valid) {
#pragma unroll
                    for (int n = 0; n < NN; n++)
                        g_smq[((size_t)(q0 + qi) * NN + n) * TT + t0c + trel] = sigm(r[n]);
                }
            }
            __threadfence();
            __syncthreads();
            if (tid < QG) atomicAdd(&g_bq_done[q0 + tid], 1u);
        } else if (task < T4E) {
            // ===== T4: shot map_s partials (waits wc/wt) =====
            int s2 = task - TBE;
            int bn = s2 / SCH, ch = s2 % SCH;
            int b = bn / NN;
            int t0 = ch * 40, t1 = min(KT, t0 + 40);
            float* SVV = dyn; float* PW = dyn + CC;
            waitCnt(&g_wcwt_done, NFIN);
            SVV[tid] = g_wc[bn * CC + tid] * g_wt[b * CC + tid];
            __syncthreads();

            float acc[12];
#pragma unroll
            for (int e = 0; e < 12; e++) acc[e] = 0.0f;
            for (int t = t0 + w; t < t1; t += NW) {
                const float* fp = fshot + ((size_t)bn * KT + t) * CC + 4 * lane;
                float fv[12];
#pragma unroll
                for (int j = 0; j < 3; j++) {
                    float4 u = *(const float4*)(fp + 128 * j);
                    fv[4*j] = u.x; fv[4*j+1] = u.y; fv[4*j+2] = u.z; fv[4*j+3] = u.w;
                }
                float r[1] = {0.0f};
#pragma unroll
                for (int j = 0; j < 3; j++) {
                    float4 u = *(const float4*)(&SVV[128 * j + 4 * lane]);
                    r[0] += fv[4*j]*u.x + fv[4*j+1]*u.y + fv[4*j+2]*u.z + fv[4*j+3]*u.w;
                }
                warpRed<1>(r);
                float ms = sigm(r[0]);
#pragma unroll
                for (int e = 0; e < 12; e++) acc[e] += fv[e] * ms;
            }
#pragma unroll
            for (int e = 0; e < 12; e++) {
                int c = 128 * (e >> 2) + (lane << 2) + (e & 3);
                PW[w * CC + c] = acc[e];
            }
            __syncthreads();
            float s = 0.0f;
#pragma unroll
            for (int ww = 0; ww < NW; ww++) s += PW[ww * CC + tid];
            g_shot_part[(size_t)s2 * CC + tid] = s;
            signal1(&g_shot_done);
        } else {
            // ===== T6: finals =====
            int bq = task - T4E;
            int b = bq / QQ;
            float* SMQ5 = dyn;                      // NN*TT = 980
            float* PW4  = dyn + NN*TT;              // 4*NN*CC = 7680
            float* CW   = PW4 + 4*NN*CC;            // NW*21
            float* TOT  = CW + NW*21;
            if (tid == 0) {
                while (*(volatile unsigned*)&g_shot_done < (unsigned)SHOT_TGT) __nanosleep(32);
                while (*(volatile unsigned*)&g_bq_done[bq] < (unsigned)BQ_TGT) __nanosleep(32);
            }
            __syncthreads();
            for (int i = tid; i < NN * TT; i += 384)
                SMQ5[i] = g_smq[(size_t)bq * NN * TT + i];
            __syncthreads();

            if (tid == 0) {
                float s = 0.0f;
#pragma unroll
                for (int n = 0; n < NN; n++) {
                    float mm = -3.4e38f;
                    for (int ch = 0; ch < NCHK; ch++)
                        mm = fmaxf(mm, g_mx_part[((size_t)ch * BQ + bq) * NN + n]);
                    s += mm;
                }
                s *= (1.0f / NN);
                out[bq] = s;
                out[BQ + bq] = s;
            }

            {
                int tq = tid / 96, c4 = tid % 96;
                u64 accp[NN][2];
#pragma unroll
                for (int n = 0; n < NN; n++) { accp[n][0] = 0ull; accp[n][1] = 0ull; }
                const float* fp4 = fq + ((size_t)bq * TT + tq * 49) * CC + c4 * 4;
#pragma unroll 7
                for (int t = 0; t < 49; t++) {
                    ulonglong2 a = *(const ulonglong2*)(fp4 + (size_t)t * CC);
#pragma unroll
                    for (int n = 0; n < NN; n++) {
                        float s = SMQ5[n * TT + tq * 49 + t];
                        u64 ss = pk2(s, s);
                        ffma2(accp[n][0], a.x, ss);
                        ffma2(accp[n][1], a.y, ss);
                    }
                }
#pragma unroll
                for (int n = 0; n < NN; n++) {
                    float l0, h0, l1, h1;
                    unpk2(accp[n][0], l0, h0);
                    unpk2(accp[n][1], l1, h1);
                    float* p = PW4 + (tq * NN + n) * CC + c4 * 4;
                    p[0] = l0; p[1] = h0; p[2] = l1; p[3] = h1;
                }
            }
            __syncthreads();

            float acc[NN];
#pragma unroll
            for (int n = 0; n < NN; n++) {
                float s = 0.0f;
#pragma unroll
                for (int q2 = 0; q2 < 4; q2++) s += PW4[(q2 * NN + n) * CC + tid];
                acc[n] = s;
            }

            float xqv = xq_in[(size_t)bq * CC + tid];
            float pv[21];
            pv[0] = xqv * xqv;
#pragma unroll
            for (int n = 0; n < NN; n++) {
                float wcv = g_wc[(b * NN + n) * CC + tid];
                float sp = 0.0f;
#pragma unroll
                for (int ch = 0; ch < SCH; ch++)
                    sp += g_shot_part[(size_t)((b * NN + n) * SCH + ch) * CC + tid];
                float xsr = wcv * sp * (1.0f / KT);
                float xqr = wcv * acc[n] * (1.0f / TT);
                pv[1 + n]  = xqv * g_xs2_hat[(b * NN + n) * CC + tid];
                pv[6 + n]  = xqr * xqr;
                pv[11 + n] = xqr * xsr;
                pv[16 + n] = xsr * xsr;
            }
            warpRed<21>(pv);
            if (lane == 0) {
#pragma unroll
                for (int k = 0; k < 21; k++) CW[w * 21 + k] = pv[k];
            }
            __syncthreads();
            if (tid < 21) {
                float s = 0.0f;
#pragma unroll
                for (int ww = 0; ww < NW; ww++) s += CW[ww * 21 + tid];
                TOT[tid] = s;
            }
            __syncthreads();
            if (tid < NN) {
                float nq2 = fmaxf(sqrtf(TOT[0]), 1e-12f);
                out[2 * BQ + bq * NN + tid] = TEMPF * TOT[1 + tid] / nq2;
                out[2 * BQ + BQ * NN + bq * NN + tid] =
                    TOT[11 + tid] / ((1e-16f + sqrtf(TOT[6 + tid])) * (1e-16f + sqrtf(TOT[16 + tid])));
            }
        }
    }

    // drain, then reset all counters for next graph replay
    gridBar();
    if (blockIdx.x == 0) {
        if (tid < BQ) g_bq_done[tid] = 0u;
        if (tid < BB*NN) g_meanbn_done[tid] = 0u;
        if (tid < NFIN) g_mlprow_done[tid] = 0u;
        if (tid < BB) g_meanb_done[tid] = 0u;
        if (tid == 0) {
            g_wcwt_done = 0u; g_shot_done = 0u; g_task = 0u;
        }
    }
}

extern "C" void kernel_launch(void* const* d_in, const int* in_sizes, int n_in,
                              void* d_out, int out_size) {
    const float* feat_shot  = (const float*)d_in[0];
    const float* feat_query = (const float*)d_in[1];
    const float* x_shot     = (const float*)d_in[2];
    const float* x_query    = (const float*)d_in[3];
    const float* w1_task    = (const float*)d_in[4];
    const float* b1_task    = (const float*)d_in[5];
    const float* w2_task    = (const float*)d_in[6];
    const float* b2_task    = (const float*)d_in[7];
    const float* w1_cls     = (const float*)d_in[8];
    const float* b1_cls     = (const float*)d_in[9];
    const float* w2_cls     = (const float*)d_in[10];
    const float* b2_cls     = (const float*)d_in[11];
    float* out = (float*)d_out;

    cudaFuncSetAttribute(kFused, cudaFuncAttributeMaxDynamicSharedMemorySize, DYN_BYTES);

    int dev = 0;
    cudaGetDevice(&dev);
    int sms = 0;
    cudaDeviceGetAttribute(&sms, cudaDevAttrMultiProcessorCount, dev);
    int maxBlk = 1;
    cudaOccupancyMaxActiveBlocksPerMultiprocessor(&maxBlk, kFused, 384, DYN_BYTES);
    if (maxBlk < 1) maxBlk = 1;
    int grid = sms * maxBlk;

    kFused<<<grid, 384, DYN_BYTES>>>(feat_shot, feat_query, x_shot, x_query,
                                     w1_task, b1_task, w2_task, b2_task,
                                     w1_cls, b1_cls, w2_cls, b2_cls, out);
}